// round 6
// baseline (speedup 1.0000x reference)
#include <cuda_runtime.h>
#include <cuda_bf16.h>
#include <cuda_fp8.h>
#include <cstdint>

#define N_PTS 9216
#define DD 256
#define KSUB 64            // screening subset: dims 0..63 (d2_full >= d2_sub, strict)
#define GRID_T 72
#define NT 2628            // 72*73/2 triangular tiles
#define PAIR_BLOCKS 304    // persistent, 2/SM
#define ASTR 80            // smem row stride bytes (64B data + 16B pad, conflict-free LDSM)
#define BUFSZ (128 * ASTR) // 10240 B per tile side
#define POSV ((float)(1.0 / 360.0))
#define NEGV ((float)(-0.5 / 8855.0))

__device__ uint8_t g_X8[N_PTS * KSUB];     // e4m3 of first 64 dims
__device__ float g_sq[N_PTS];              // full 256-dim fp32 norms (rescue)
__device__ float g_sq8[N_PTS];             // subset norms of DEQUANTIZED values (exact screen)
__device__ float g_partials[PAIR_BLOCKS];

#define CP_ASYNC16(dst, src) asm volatile("cp.async.cg.shared.global [%0], [%1], 16;" :: "r"(dst), "l"(src))
#define CP_COMMIT() asm volatile("cp.async.commit_group;" ::: "memory")
#define CP_WAIT1()  asm volatile("cp.async.wait_group 1;" ::: "memory")

// ---------------- prep: quantize 64 dims + both norms (4 rows/warp) --------
__global__ void __launch_bounds__(256) prep_kernel(const float* __restrict__ images) {
    int wid = threadIdx.x >> 5, lane = threadIdx.x & 31;
    int row = blockIdx.x * 32 + wid * 4;
    float4 v[4][2];
    #pragma unroll
    for (int rr = 0; rr < 4; rr++) {
        const float4* s = (const float4*)(images + (size_t)(row + rr) * DD);
        v[rr][0] = s[lane * 2];
        v[rr][1] = s[lane * 2 + 1];
    }
    float n[4];
    #pragma unroll
    for (int rr = 0; rr < 4; rr++) {
        float4 a = v[rr][0], b = v[rr][1];
        n[rr] = a.x*a.x + a.y*a.y + a.z*a.z + a.w*a.w
              + b.x*b.x + b.y*b.y + b.z*b.z + b.w*b.w;
    }
    #pragma unroll
    for (int o = 16; o > 0; o >>= 1)
        #pragma unroll
        for (int rr = 0; rr < 4; rr++)
            n[rr] += __shfl_xor_sync(0xffffffffu, n[rr], o);
    if (lane == 0) {
        #pragma unroll
        for (int rr = 0; rr < 4; rr++) g_sq[row + rr] = n[rr];
    }

    float s8[4] = {0.f, 0.f, 0.f, 0.f};
    if (lane < 8) {     // lanes 0..7 own dims 8*lane..8*lane+7
        #pragma unroll
        for (int rr = 0; rr < 4; rr++) {
            float va[8] = {v[rr][0].x, v[rr][0].y, v[rr][0].z, v[rr][0].w,
                           v[rr][1].x, v[rr][1].y, v[rr][1].z, v[rr][1].w};
            uint32_t q[2] = {0, 0};
            #pragma unroll
            for (int k = 0; k < 8; k++) {
                uint8_t e = __nv_cvt_float_to_fp8(va[k], __NV_SATFINITE, __NV_E4M3);
                q[k >> 2] |= (uint32_t)e << ((k & 3) * 8);
                float dq = __half2float(__nv_cvt_fp8_to_halfraw(e, __NV_E4M3));
                s8[rr] = fmaf(dq, dq, s8[rr]);
            }
            *(uint2*)(g_X8 + (size_t)(row + rr) * KSUB + lane * 8) = make_uint2(q[0], q[1]);
        }
    }
    #pragma unroll
    for (int o = 16; o > 0; o >>= 1)
        #pragma unroll
        for (int rr = 0; rr < 4; rr++)
            s8[rr] += __shfl_xor_sync(0xffffffffu, s8[rr], o);
    if (lane == 0) {
        #pragma unroll
        for (int rr = 0; rr < 4; rr++) g_sq8[row + rr] = s8[rr];
    }
}

// correction = sim(d2) + 1.0027, exact fp32, for d2 <= 16
__device__ __forceinline__ float corr_fn(float d2) {
    d2 = fmaxf(d2, 0.0f);
    float dist = (d2 > 0.0f) ? sqrtf(d2) : 0.0f;
    float t = 5.0f * (1.0f - dist);
    float sp = (t > 0.0f) ? (t + log1pf(expf(-t))) : log1pf(expf(t));
    return 0.4f * sp;
}
__device__ __forceinline__ float maskval(int i, int j) {
    int ci0 = i / 96, ci1 = i - ci0 * 96;
    int cj0 = j / 96, cj1 = j - cj0 * 96;
    int d0 = abs(ci0 - cj0); d0 = min(d0, 96 - d0);
    int d1 = abs(ci1 - cj1); d1 = min(d1, 96 - d1);
    return (d0 <= 9 && d1 <= 9) ? POSV : NEGV;
}
__device__ __forceinline__ void decode_tile(int t, int& by, int& bx) {
    int b = 0, rem = t;
    while (rem >= GRID_T - b) { rem -= GRID_T - b; b++; }
    by = b; bx = b + rem;
}

// ---------------- persistent double-buffered screening GEMM ----------------
__global__ void __launch_bounds__(256, 2)
pair_kernel(const float* __restrict__ images) {
    __shared__ uint8_t Abuf[2][BUFSZ];
    __shared__ uint8_t Bbuf[2][BUFSZ];
    __shared__ float nIbuf[2][128];
    __shared__ float nJbuf[2][128];
    __shared__ float wsum[8];

    int tid  = threadIdx.x;
    int wid  = tid >> 5;
    int lane = tid & 31;
    int g  = lane >> 2;
    int tg = lane & 3;
    int wm = (wid >> 1) * 32;
    int wn = (wid & 1) * 64;

    uint32_t A_u, B_u, NI_u, NJ_u;
    asm("{ .reg .u64 t; cvta.to.shared.u64 t, %1; cvt.u32.u64 %0, t; }" : "=r"(A_u)  : "l"(&Abuf[0][0]));
    asm("{ .reg .u64 t; cvta.to.shared.u64 t, %1; cvt.u32.u64 %0, t; }" : "=r"(B_u)  : "l"(&Bbuf[0][0]));
    asm("{ .reg .u64 t; cvta.to.shared.u64 t, %1; cvt.u32.u64 %0, t; }" : "=r"(NI_u) : "l"(&nIbuf[0][0]));
    asm("{ .reg .u64 t; cvta.to.shared.u64 t, %1; cvt.u32.u64 %0, t; }" : "=r"(NJ_u) : "l"(&nJbuf[0][0]));

    int ldr_r = tid >> 1, ldr_h = (tid & 1) * 32;
    int quad = lane >> 3, rw = lane & 7;
    uint32_t aOff = (uint32_t)((wm + rw + (quad & 1) * 8) * ASTR + (quad >> 1) * 16);
    uint32_t bOff = (uint32_t)((wn + rw + ((quad >> 1) & 1) * 8) * ASTR + (quad & 1) * 16);

    // issue loads for tile (i0,j0) into buffer bf
    auto issue = [&](int i0, int j0, int bf) {
        const uint8_t* sa = g_X8 + (size_t)(i0 + ldr_r) * KSUB + ldr_h;
        const uint8_t* sb = g_X8 + (size_t)(j0 + ldr_r) * KSUB + ldr_h;
        uint32_t da = A_u + bf * BUFSZ + ldr_r * ASTR + ldr_h;
        uint32_t db = B_u + bf * BUFSZ + ldr_r * ASTR + ldr_h;
        CP_ASYNC16(da, sa);
        CP_ASYNC16(da + 16, sa + 16);
        CP_ASYNC16(db, sb);
        CP_ASYNC16(db + 16, sb + 16);
        if (tid < 32)
            CP_ASYNC16(NI_u + bf * 512 + tid * 16, (const uint8_t*)(g_sq8 + i0) + tid * 16);
        else if (tid < 64)
            CP_ASYNC16(NJ_u + bf * 512 + (tid - 32) * 16, (const uint8_t*)(g_sq8 + j0) + (tid - 32) * 16);
    };

    float local = 0.0f;

    int t0 = blockIdx.x;
    if (t0 < NT) {
        int by, bx;
        decode_tile(t0, by, bx);
        issue(by * 128, bx * 128, 0);
    }
    CP_COMMIT();

    for (int t = t0; t < NT; t += PAIR_BLOCKS) {
        int cur = ((t - t0) / PAIR_BLOCKS) & 1;
        int by, bx;
        decode_tile(t, by, bx);
        int i0 = by * 128, j0 = bx * 128;

        // prefetch next tile (duplicate current on final iter — harmless)
        int tn = (t + PAIR_BLOCKS < NT) ? t + PAIR_BLOCKS : t;
        int byn, bxn;
        decode_tile(tn, byn, bxn);
        issue(byn * 128, bxn * 128, cur ^ 1);
        CP_COMMIT();
        CP_WAIT1();             // current buffer complete
        __syncthreads();

        uint32_t aAddr = A_u + cur * BUFSZ + aOff;
        uint32_t bAddr = B_u + cur * BUFSZ + bOff;

        float acc[2][8][4];
        #pragma unroll
        for (int a = 0; a < 2; a++)
            #pragma unroll
            for (int b = 0; b < 8; b++)
                #pragma unroll
                for (int c = 0; c < 4; c++) acc[a][b][c] = 0.0f;

        #pragma unroll
        for (int ksb = 0; ksb < KSUB; ksb += 32) {     // 2 k32 steps
            uint32_t afr[2][4];
            #pragma unroll
            for (int mf = 0; mf < 2; mf++) {
                uint32_t ad = aAddr + (uint32_t)(mf * 16 * ASTR + ksb);
                asm volatile("ldmatrix.sync.aligned.m8n8.x4.shared.b16 {%0,%1,%2,%3}, [%4];"
                             : "=r"(afr[mf][0]), "=r"(afr[mf][1]),
                               "=r"(afr[mf][2]), "=r"(afr[mf][3]) : "r"(ad));
            }
            uint32_t bfr[8][2];
            #pragma unroll
            for (int p = 0; p < 4; p++) {
                uint32_t bd = bAddr + (uint32_t)(p * 16 * ASTR + ksb);
                asm volatile("ldmatrix.sync.aligned.m8n8.x4.shared.b16 {%0,%1,%2,%3}, [%4];"
                             : "=r"(bfr[2 * p][0]), "=r"(bfr[2 * p][1]),
                               "=r"(bfr[2 * p + 1][0]), "=r"(bfr[2 * p + 1][1]) : "r"(bd));
            }
            #pragma unroll
            for (int mf = 0; mf < 2; mf++)
                #pragma unroll
                for (int nf = 0; nf < 8; nf++) {
                    asm volatile(
                        "mma.sync.aligned.m16n8k32.row.col.f32.e4m3.e4m3.f32 "
                        "{%0,%1,%2,%3}, {%4,%5,%6,%7}, {%8,%9}, {%0,%1,%2,%3};\n"
                        : "+f"(acc[mf][nf][0]), "+f"(acc[mf][nf][1]),
                          "+f"(acc[mf][nf][2]), "+f"(acc[mf][nf][3])
                        : "r"(afr[mf][0]), "r"(afr[mf][1]),
                          "r"(afr[mf][2]), "r"(afr[mf][3]),
                          "r"(bfr[nf][0]), "r"(bfr[nf][1]));
                }
        }

        // ---- epilogue: exact quantized-space screen, d2hat <= 32 => rescue ----
        const float* nI = nIbuf[cur];
        const float* nJ = nJbuf[cur];
        #pragma unroll
        for (int mf = 0; mf < 2; mf++) {
            int r0 = wm + mf * 16 + g;
            float sqa = nI[r0];
            float sqb = nI[r0 + 8];
            #pragma unroll
            for (int nf = 0; nf < 8; nf++) {
                int cl = wn + nf * 8 + 2 * tg;
                float sj0 = nJ[cl];
                float sj1 = nJ[cl + 1];
                float d00 = fmaf(-2.0f, acc[mf][nf][0], sqa + sj0);
                float d01 = fmaf(-2.0f, acc[mf][nf][1], sqa + sj1);
                float d10 = fmaf(-2.0f, acc[mf][nf][2], sqb + sj0);
                float d11 = fmaf(-2.0f, acc[mf][nf][3], sqb + sj1);
                float mn = fminf(fminf(d00, d01), fminf(d10, d11));
                if (mn <= 32.0f) {        // ~only diagonal fragments trigger
                    #pragma unroll
                    for (int q = 0; q < 4; q++) {
                        float d2f = (q == 0) ? d00 : (q == 1) ? d01 : (q == 2) ? d10 : d11;
                        if (d2f <= 32.0f) {
                            int i = i0 + r0 + (q >> 1) * 8;
                            int j = j0 + cl + (q & 1);
                            if (i < j) {  // count once, weight x2 (symmetry)
                                const float4* xa = (const float4*)(images + (size_t)i * DD);
                                const float4* xb = (const float4*)(images + (size_t)j * DD);
                                float dot = 0.0f;
                                #pragma unroll 8
                                for (int u = 0; u < 64; u++) {
                                    float4 a = xa[u], b = xb[u];
                                    dot = fmaf(a.x, b.x, dot); dot = fmaf(a.y, b.y, dot);
                                    dot = fmaf(a.z, b.z, dot); dot = fmaf(a.w, b.w, dot);
                                }
                                float d2 = fmaxf(g_sq[i] + g_sq[j] - 2.0f * dot, 0.0f);
                                if (d2 <= 16.0f)
                                    local = fmaf(2.0f * corr_fn(d2), maskval(i, j), local);
                            }
                        }
                    }
                }
            }
        }
        __syncthreads();   // all reads of buf[cur] done before next iter overwrites it
    }

    #pragma unroll
    for (int o = 16; o > 0; o >>= 1) local += __shfl_xor_sync(0xffffffffu, local, o);
    if (lane == 0) wsum[wid] = local;
    __syncthreads();
    if (tid == 0) {
        float s = 0.0f;
        #pragma unroll
        for (int w = 0; w < 8; w++) s += wsum[w];
        g_partials[blockIdx.x] = s;
    }
}

// ---------------- final reduce + closed-form base term ---------------------
__global__ void reduce_kernel(float* __restrict__ out) {
    int t = threadIdx.x;  // 256
    float s = (t < PAIR_BLOCKS) ? g_partials[t] : 0.0f;
    if (t + 256 < PAIR_BLOCKS) s += g_partials[t + 256];
    #pragma unroll
    for (int o = 16; o > 0; o >>= 1) s += __shfl_xor_sync(0xffffffffu, s, o);
    __shared__ float ws[8];
    if ((t & 31) == 0) ws[t >> 5] = s;
    __syncthreads();
    if (t == 0) {
        float tot = 0.0f;
        #pragma unroll
        for (int w = 0; w < 8; w++) tot += ws[w];
        // off-diag sim == -1.0027f exactly; sum(mask) = N*(360*POSV + 8855*NEGV)
        double masksum = 9216.0 * (360.0 * (double)POSV + 8855.0 * (double)NEGV);
        double base = (double)(-1.0027f) * masksum;
        out[0] = (float)(((double)tot + base) / 9216.0);
    }
}

extern "C" void kernel_launch(void* const* d_in, const int* in_sizes, int n_in,
                              void* d_out, int out_size) {
    const float* images = (const float*)d_in[0];   // [9216,1,16,16] fp32
    (void)in_sizes; (void)n_in;
    prep_kernel<<<288, 256>>>(images);
    pair_kernel<<<PAIR_BLOCKS, 256>>>(images);
    reduce_kernel<<<1, 256>>>((float*)d_out);
}